// round 1
// baseline (speedup 1.0000x reference)
#include <cuda_runtime.h>
#include <cstdint>
#include <cstdio>
#include <math.h>

// Problem constants
#define Bq 128
#define Tq 2048
#define Dq 128
#define Hq 512
#define Lq 10

// Kernel geometry
#define NBLK 128        // 8 batch-tiles x 16 j-tiles, all co-resident (<=148 SMs)
#define NTHREADS 128
#define BT 16           // batch rows per block
#define JT 32           // hidden-j per block (x4 gates = 128 output cols)
#define KIN 640         // inner dim = H (512) + D (128)
#define KTILE 64
#define NKT 10          // 640 / 64

// Shared memory layout (floats)
#define SM_AS   (BT*KIN)        // 10240 : A matrix [b][k] (h then x_t)
#define SM_WS   (KTILE*128)     // 8192  : one W tile [k][col]
#define SM_GS   (BT*128)        // 2048  : gates staging
#define SM_CS   (BT*JT)         // 512   : cell state
#define SM_TOTAL (SM_AS + 2*SM_WS + SM_GS + SM_CS)   // 29184 floats = 116736 B

// Device scratch (allowed: __device__ globals, no runtime allocation)
__device__ float g_h[2][Bq * Hq];                 // double-buffered hidden state
__device__ float g_Wt[16 * KIN * 128];            // W reordered: [jt][k][col], col = gate*32+jj
__device__ unsigned g_bar;                        // monotonic grid barrier counter

// ---------------------------------------------------------------------------
// Init kernel: zero barrier + h0, and reorder W_hh/W_ih into g_Wt so that each
// per-block weight tile is a contiguous 32KB chunk (coalesced cp.async loads).
// Runs every launch (deterministic; cheap vs 2048-step scan).
// ---------------------------------------------------------------------------
__global__ void init_kernel(const float* __restrict__ W_ih,
                            const float* __restrict__ W_hh) {
    unsigned idx = blockIdx.x * blockDim.x + threadIdx.x;
    unsigned stride = gridDim.x * blockDim.x;
    if (idx == 0) g_bar = 0u;
    for (unsigned i = idx; i < Bq * Hq; i += stride) g_h[0][i] = 0.f;

    const unsigned total = 16u * KIN * 128u;
    for (unsigned i = idx; i < total; i += stride) {
        unsigned jt  = i / (KIN * 128);
        unsigned r   = i - jt * (KIN * 128);
        unsigned k   = r >> 7;
        unsigned col = r & 127u;
        unsigned gate = col >> 5, jj = col & 31u;
        unsigned row = gate * Hq + jt * JT + jj;
        g_Wt[i] = (k < Hq) ? W_hh[row * Hq + k]
                           : W_ih[row * Dq + (k - Hq)];
    }
}

__device__ __forceinline__ unsigned smem_u32(const void* p) {
    return (unsigned)__cvta_generic_to_shared(p);
}

// Copy one 64x128 fp32 W tile (32KB, contiguous in g_Wt) global->shared.
__device__ __forceinline__ void tile_cp_async(float* dst, const float* src, int tid) {
    unsigned s = smem_u32(dst);
#pragma unroll
    for (int i = 0; i < 16; i++) {
        int q = tid + i * NTHREADS;   // float4 index, 2048 total
        asm volatile("cp.async.cg.shared.global [%0], [%1], 16;\n"
                     :: "r"(s + q * 16), "l"(src + q * 4) : "memory");
    }
}

__device__ __forceinline__ float sigmoidf_(float v) {
    return 1.f / (1.f + expf(-v));
}

// ---------------------------------------------------------------------------
// Persistent LSTM kernel. Block = (bt, jt):
//   bt = blockIdx/16 -> batch rows [bt*16, bt*16+16)
//   jt = blockIdx%16 -> hidden cols [jt*32, jt*32+32), all 4 gates
// Per step: C(16x128) = A(16x640) * Wt(640x128), fused bias; LSTM elementwise
// with block-local c; write h chunk to other parity buffer; grid barrier.
// ---------------------------------------------------------------------------
__global__ __launch_bounds__(NTHREADS, 1)
void lstm_kernel(const float* __restrict__ x,
                 const float* __restrict__ bias,
                 const float* __restrict__ Wout,
                 float* __restrict__ out) {
    extern __shared__ float sm[];
    float* as  = sm;                 // [16][640]
    float* ws0 = as + SM_AS;         // [64][128]
    float* ws1 = ws0 + SM_WS;
    float* gsh = ws1 + SM_WS;        // [16][128]
    float* csh = gsh + SM_GS;        // [16][32]

    const int tid  = threadIdx.x;
    const int bt   = blockIdx.x >> 4;
    const int jt   = blockIdx.x & 15;
    const int lane = tid & 31;
    const int w    = tid >> 5;
    const int c4   = lane << 2;      // output col base (0..124)
    const int b0   = w << 2;         // batch row base (0..12)
    const int bbase = bt * BT;

    for (int i = tid; i < SM_CS; i += NTHREADS) csh[i] = 0.f;

    // Per-thread bias for its 4 output columns
    float bias_r[4];
#pragma unroll
    for (int i = 0; i < 4; i++) {
        int col = c4 + i;
        int gate = col >> 5, jj = col & 31;
        bias_r[i] = bias[gate * Hq + jt * JT + jj];
    }

    const float* Wt = g_Wt + (size_t)jt * (KIN * 128);

    for (int t = 0; t < Tq; ++t) {
        const int p = t & 1;
        const float* __restrict__ hin  = g_h[p];
        float* __restrict__ hout       = g_h[p ^ 1];

        // Prefetch first W tile while loading A
        tile_cp_async(ws0, Wt, tid);
        asm volatile("cp.async.commit_group;\n" ::: "memory");

        // A = [h (512) | x_t (128)] for 16 batch rows
        for (int i = tid; i < BT * Hq; i += NTHREADS) {
            int b = i >> 9, k = i & (Hq - 1);
            as[b * KIN + k] = hin[(bbase + b) * Hq + k];
        }
        for (int i = tid; i < BT * Dq; i += NTHREADS) {
            int b = i >> 7, d = i & (Dq - 1);
            as[b * KIN + Hq + d] = x[((size_t)(bbase + b) * Tq + t) * Dq + d];
        }

        float acc[4][4];
#pragma unroll
        for (int i = 0; i < 4; i++)
#pragma unroll
            for (int j = 0; j < 4; j++) acc[i][j] = bias_r[j];

#pragma unroll 1
        for (int kt2 = 0; kt2 < NKT; ++kt2) {
            const float* wcur = (kt2 & 1) ? ws1 : ws0;
            float* wnxt       = (kt2 & 1) ? ws0 : ws1;
            if (kt2 < NKT - 1) {
                tile_cp_async(wnxt, Wt + (size_t)(kt2 + 1) * SM_WS, tid);
                asm volatile("cp.async.commit_group;\n" ::: "memory");
                asm volatile("cp.async.wait_group 1;\n" ::: "memory");
            } else {
                asm volatile("cp.async.wait_group 0;\n" ::: "memory");
            }
            __syncthreads();   // tile (and, at kt2==0, A) visible to all threads

            const int kb = kt2 * KTILE;
            const float* a0p = as + (b0 + 0) * KIN + kb;
            const float* a1p = as + (b0 + 1) * KIN + kb;
            const float* a2p = as + (b0 + 2) * KIN + kb;
            const float* a3p = as + (b0 + 3) * KIN + kb;
#pragma unroll 8
            for (int k = 0; k < KTILE; ++k) {
                float4 wv = *reinterpret_cast<const float4*>(wcur + k * 128 + c4);
                float a0 = a0p[k], a1 = a1p[k], a2 = a2p[k], a3 = a3p[k];
                acc[0][0] += a0 * wv.x; acc[0][1] += a0 * wv.y; acc[0][2] += a0 * wv.z; acc[0][3] += a0 * wv.w;
                acc[1][0] += a1 * wv.x; acc[1][1] += a1 * wv.y; acc[1][2] += a1 * wv.z; acc[1][3] += a1 * wv.w;
                acc[2][0] += a2 * wv.x; acc[2][1] += a2 * wv.y; acc[2][2] += a2 * wv.z; acc[2][3] += a2 * wv.w;
                acc[3][0] += a3 * wv.x; acc[3][1] += a3 * wv.y; acc[3][2] += a3 * wv.z; acc[3][3] += a3 * wv.w;
            }
            __syncthreads();   // done with wcur before it is refilled
        }

        // Stage gates, then elementwise LSTM update
#pragma unroll
        for (int i = 0; i < 4; i++) {
            *reinterpret_cast<float4*>(&gsh[(b0 + i) * 128 + c4]) =
                make_float4(acc[i][0], acc[i][1], acc[i][2], acc[i][3]);
        }
        __syncthreads();

        for (int pp = tid; pp < BT * JT; pp += NTHREADS) {
            int b = pp >> 5, jj = pp & 31;
            const float* gr = gsh + b * 128;
            float iS = sigmoidf_(gr[jj]);
            float fS = sigmoidf_(gr[32 + jj]);
            float gT = tanhf(gr[64 + jj]);
            float oS = sigmoidf_(gr[96 + jj]);
            float cn = fS * csh[pp] + iS * gT;
            csh[pp] = cn;
            hout[(bbase + b) * Hq + jt * JT + jj] = oS * tanhf(cn);
        }

        // Grid barrier (monotonic counter; all 128 blocks co-resident)
        __threadfence();
        __syncthreads();
        if (tid == 0) {
            atomicAdd(&g_bar, 1u);
            unsigned target = (unsigned)(t + 1) * (unsigned)NBLK;
            while (*((volatile unsigned*)&g_bar) < target) { }
        }
        __syncthreads();
    }

    // Output head: blocks with jt==0 compute logits + softmax for their batches.
    // Final h lives in g_h[0] (Tq even), complete after last barrier.
    if (jt == 0) {
        for (int i = tid; i < BT * Hq; i += NTHREADS) {
            int b = i >> 9, k = i & (Hq - 1);
            as[b * Hq + k] = g_h[0][(bbase + b) * Hq + k];
        }
        __syncthreads();
        for (int q = tid; q < BT * Lq; q += NTHREADS) {
            int b = q / Lq, l = q - b * Lq;
            const float* hr = as + b * Hq;
            const float* wr = Wout + l * Hq;
            float s = 0.f;
            for (int k = 0; k < Hq; k++) s += hr[k] * wr[k];
            gsh[b * Lq + l] = s;
        }
        __syncthreads();
        if (tid < BT) {
            int b = tid;
            float m = -1e30f;
            for (int l = 0; l < Lq; l++) m = fmaxf(m, gsh[b * Lq + l]);
            float e[Lq]; float ssum = 0.f;
            for (int l = 0; l < Lq; l++) { e[l] = expf(gsh[b * Lq + l] - m); ssum += e[l]; }
            float inv = 1.f / ssum;
            for (int l = 0; l < Lq; l++) out[(bbase + b) * Lq + l] = e[l] * inv;
        }
    }
}

extern "C" void kernel_launch(void* const* d_in, const int* in_sizes, int n_in,
                              void* d_out, int out_size) {
    const float* x     = (const float*)d_in[0];   // (B,T,D)
    const float* W_ih  = (const float*)d_in[1];   // (4H,D)
    const float* W_hh  = (const float*)d_in[2];   // (4H,H)
    const float* b     = (const float*)d_in[3];   // (4H)
    const float* W_out = (const float*)d_in[4];   // (L,H)
    float* out = (float*)d_out;                   // (B,L)

    cudaFuncSetAttribute(lstm_kernel,
                         cudaFuncAttributeMaxDynamicSharedMemorySize,
                         SM_TOTAL * (int)sizeof(float));

    init_kernel<<<256, 256>>>(W_ih, W_hh);
    lstm_kernel<<<NBLK, NTHREADS, SM_TOTAL * (int)sizeof(float)>>>(x, b, W_out, out);
}

// round 2
// speedup vs baseline: 1.0035x; 1.0035x over previous
#include <cuda_runtime.h>
#include <cstdint>
#include <math.h>

// Problem constants
#define Bq 128
#define Tq 2048
#define Dq 128
#define Hq 512
#define Lq 10

// Geometry: 128 persistent blocks = 4 batch-tiles (BT=32) x 32 j-tiles (JT=16)
#define NBLK 128
#define NTHREADS 256
#define BT 32
#define JT 16
#define CC 64            // output cols per block = 4 gates x JT
#define KIN 640          // H + D
#define KCH 160          // A chunk length (4 chunks)
#define NCH 4

// Shared memory (floats)
#define SM_W   (KIN*CC)        // 40960 : resident weights [k][col]
#define SM_A   (BT*KCH)        // 5120  : one A chunk [b][kchunk]
#define SM_G   (BT*CC)         // 2048  : gates staging
#define SM_C   (BT*JT)         // 512   : cell state
#define SM_TOTAL (SM_W + 2*SM_A + SM_G + SM_C)   // 53760 floats = 215040 B

__device__ float g_h[2][Bq * Hq];        // double-buffered hidden state
__device__ float g_Wt[32 * KIN * CC];    // reordered weights: [jt][k][col]
__device__ unsigned g_bar;               // monotonic grid barrier

typedef unsigned long long ull;

// ---------------------------------------------------------------------------
__global__ void init_kernel(const float* __restrict__ W_ih,
                            const float* __restrict__ W_hh) {
    unsigned idx = blockIdx.x * blockDim.x + threadIdx.x;
    unsigned stride = gridDim.x * blockDim.x;
    if (idx == 0) g_bar = 0u;
    for (unsigned i = idx; i < Bq * Hq; i += stride) g_h[0][i] = 0.f;

    const unsigned total = 32u * KIN * CC;
    for (unsigned i = idx; i < total; i += stride) {
        unsigned jt  = i / (KIN * CC);
        unsigned r   = i - jt * (KIN * CC);
        unsigned k   = r / CC;
        unsigned col = r - k * CC;
        unsigned gate = col >> 4, jj = col & 15u;
        unsigned row = gate * Hq + jt * JT + jj;
        g_Wt[i] = (k < Hq) ? W_hh[row * Hq + k]
                           : W_ih[row * Dq + (k - Hq)];
    }
}

__device__ __forceinline__ unsigned smem_u32(const void* p) {
    return (unsigned)__cvta_generic_to_shared(p);
}
__device__ __forceinline__ void ffma2(ull& d, ull a, ull b) {
    asm("fma.rn.f32x2 %0, %1, %2, %0;" : "+l"(d) : "l"(a), "l"(b));
}
__device__ __forceinline__ ull splat2(float v) {
    ull r; asm("mov.b64 %0, {%1, %1};" : "=l"(r) : "f"(v)); return r;
}
__device__ __forceinline__ ull pack2(float lo, float hi) {
    ull r; asm("mov.b64 %0, {%1, %2};" : "=l"(r) : "f"(lo), "f"(hi)); return r;
}
__device__ __forceinline__ void unpack2(ull v, float& lo, float& hi) {
    asm("mov.b64 {%0, %1}, %2;" : "=f"(lo), "=f"(hi) : "l"(v));
}
__device__ __forceinline__ float sigm(float v) {
    return 1.f / (1.f + __expf(-v));
}
__device__ __forceinline__ float tanh_fast(float v) {
    return 1.f - 2.f / (__expf(2.f * v) + 1.f);
}

// Load one A chunk [32 rows x 160 k] via cp.async (16B granules).
// chunk c covers kglobal [c*160, c*160+160): c<3 all h; c==3: 32 h + 128 x.
__device__ __forceinline__ void loadA(float* dst, int c, const float* hin,
                                      const float* x, int t, int bbase, int tid) {
    unsigned s = smem_u32(dst);
#pragma unroll
    for (int i = 0; i < 5; i++) {
        int q = tid + i * NTHREADS;        // 0..1279 (row*40 + f4)
        int row = q / 40;
        int f4 = q - row * 40;
        const float* src;
        if (c < 3)
            src = hin + (bbase + row) * Hq + c * KCH + f4 * 4;
        else if (f4 < 8)
            src = hin + (bbase + row) * Hq + 480 + f4 * 4;
        else
            src = x + ((size_t)(bbase + row) * Tq + t) * Dq + (f4 - 8) * 4;
        asm volatile("cp.async.cg.shared.global [%0], [%1], 16;\n"
                     :: "r"(s + q * 16), "l"(src) : "memory");
    }
    asm volatile("cp.async.commit_group;\n" ::: "memory");
}

// ---------------------------------------------------------------------------
__global__ __launch_bounds__(NTHREADS, 1)
void lstm_kernel(const float* __restrict__ x,
                 const float* __restrict__ bias,
                 const float* __restrict__ Wout,
                 float* __restrict__ out) {
    extern __shared__ float sm[];
    float* Wsh = sm;                 // [640][64]
    float* ab0 = Wsh + SM_W;         // [32][160]
    float* ab1 = ab0 + SM_A;
    float* gsh = ab1 + SM_A;         // [32][64]
    float* csh = gsh + SM_G;         // [32][16]

    const int tid  = threadIdx.x;
    const int bt   = blockIdx.x >> 5;          // 4 batch tiles
    const int jt   = blockIdx.x & 31;          // 32 j tiles
    const int lane = tid & 31;
    const int w    = tid >> 5;
    const int cg   = w & 1;
    const int rg   = w >> 1;
    const int cl   = cg * 32 + (lane & 7) * 4; // 4 output cols
    const int r0   = rg * 8 + (lane >> 3) * 2; // 2 batch rows
    const int bbase = bt * BT;

    // Load resident W tile (once)
    {
        const float4* src = (const float4*)(g_Wt + (size_t)jt * (KIN * CC));
        float4* dst = (float4*)Wsh;
#pragma unroll 4
        for (int i = tid; i < SM_W / 4; i += NTHREADS) dst[i] = src[i];
    }
    for (int i = tid; i < SM_C; i += NTHREADS) csh[i] = 0.f;

    // Packed bias for this thread's 4 cols
    ull bias01, bias23;
    {
        float bb[4];
#pragma unroll
        for (int i = 0; i < 4; i++) {
            int col = cl + i;
            int gate = col >> 4, jj = col & 15;
            bb[i] = bias[gate * Hq + jt * JT + jj];
        }
        bias01 = pack2(bb[0], bb[1]);
        bias23 = pack2(bb[2], bb[3]);
    }
    __syncthreads();

    for (int t = 0; t < Tq; ++t) {
        const int p = t & 1;
        const float* __restrict__ hin = g_h[p];
        float* __restrict__ hout      = g_h[p ^ 1];

        loadA(ab0, 0, hin, x, t, bbase, tid);

        ull acc00 = bias01, acc01 = bias23;   // row r0
        ull acc10 = bias01, acc11 = bias23;   // row r0+1

#pragma unroll 1
        for (int c = 0; c < NCH; ++c) {
            asm volatile("cp.async.wait_group 0;\n" ::: "memory");
            __syncthreads();
            if (c < NCH - 1)
                loadA((c & 1) ? ab0 : ab1, c + 1, hin, x, t, bbase, tid);

            const float* ab = (c & 1) ? ab1 : ab0;
            const float* ap0 = ab + r0 * KCH;
            const float* ap1 = ap0 + KCH;
            const float* wp  = Wsh + c * KCH * CC + cl;

#pragma unroll 2
            for (int k4 = 0; k4 < KCH; k4 += 4) {
                float4 a0 = *(const float4*)(ap0 + k4);
                float4 a1 = *(const float4*)(ap1 + k4);
#pragma unroll
                for (int kk = 0; kk < 4; ++kk) {
                    ulonglong2 wv = *(const ulonglong2*)(wp + (k4 + kk) * CC);
                    float a0s = (kk == 0) ? a0.x : (kk == 1) ? a0.y : (kk == 2) ? a0.z : a0.w;
                    float a1s = (kk == 0) ? a1.x : (kk == 1) ? a1.y : (kk == 2) ? a1.z : a1.w;
                    ull s0 = splat2(a0s), s1 = splat2(a1s);
                    ffma2(acc00, s0, wv.x);
                    ffma2(acc01, s0, wv.y);
                    ffma2(acc10, s1, wv.x);
                    ffma2(acc11, s1, wv.y);
                }
            }
        }

        // Stage gates
        {
            float v0, v1, v2, v3;
            unpack2(acc00, v0, v1); unpack2(acc01, v2, v3);
            *(float4*)(gsh + r0 * CC + cl) = make_float4(v0, v1, v2, v3);
            unpack2(acc10, v0, v1); unpack2(acc11, v2, v3);
            *(float4*)(gsh + (r0 + 1) * CC + cl) = make_float4(v0, v1, v2, v3);
        }
        __syncthreads();

        // Elementwise LSTM update (2 cells per thread)
#pragma unroll
        for (int u = 0; u < 2; ++u) {
            int e = tid * 2 + u;           // 0..511
            int b = e >> 4, jj = e & 15;
            const float* gr = gsh + b * CC;
            float iS = sigm(gr[jj]);
            float fS = sigm(gr[16 + jj]);
            float gT = tanh_fast(gr[32 + jj]);
            float oS = sigm(gr[48 + jj]);
            float cn = fS * csh[e] + iS * gT;
            csh[e] = cn;
            hout[(bbase + b) * Hq + jt * JT + jj] = oS * tanh_fast(cn);
        }

        // Grid barrier (128 co-resident blocks)
        __threadfence();
        __syncthreads();
        if (tid == 0) {
            atomicAdd(&g_bar, 1u);
            unsigned target = (unsigned)(t + 1) * (unsigned)NBLK;
            while (*((volatile unsigned*)&g_bar) < target) { }
        }
        __syncthreads();
    }

    // Output head: jt==0 blocks do logits + softmax for their 32 batch rows.
    if (jt == 0) {
        for (int i = tid; i < BT * Hq; i += NTHREADS) {
            int b = i >> 9, k = i & (Hq - 1);
            Wsh[b * Hq + k] = g_h[0][(bbase + b) * Hq + k];
        }
        __syncthreads();
        for (int q = tid; q < BT * Lq; q += NTHREADS) {
            int b = q / Lq, l = q - b * Lq;
            const float* hr = Wsh + b * Hq;
            const float* wr = Wout + l * Hq;
            float s = 0.f;
            for (int k = 0; k < Hq; k++) s += hr[k] * wr[k];
            gsh[b * Lq + l] = s;
        }
        __syncthreads();
        if (tid < BT) {
            int b = tid;
            float m = -1e30f;
            for (int l = 0; l < Lq; l++) m = fmaxf(m, gsh[b * Lq + l]);
            float e[Lq]; float ssum = 0.f;
            for (int l = 0; l < Lq; l++) { e[l] = expf(gsh[b * Lq + l] - m); ssum += e[l]; }
            float inv = 1.f / ssum;
            for (int l = 0; l < Lq; l++) out[(bbase + b) * Lq + l] = e[l] * inv;
        }
    }
}

extern "C" void kernel_launch(void* const* d_in, const int* in_sizes, int n_in,
                              void* d_out, int out_size) {
    const float* x     = (const float*)d_in[0];
    const float* W_ih  = (const float*)d_in[1];
    const float* W_hh  = (const float*)d_in[2];
    const float* b     = (const float*)d_in[3];
    const float* W_out = (const float*)d_in[4];
    float* out = (float*)d_out;

    cudaFuncSetAttribute(lstm_kernel,
                         cudaFuncAttributeMaxDynamicSharedMemorySize,
                         SM_TOTAL * (int)sizeof(float));

    init_kernel<<<256, 256>>>(W_ih, W_hh);
    lstm_kernel<<<NBLK, NTHREADS, SM_TOTAL * (int)sizeof(float)>>>(x, b, W_out, out);
}

// round 3
// speedup vs baseline: 1.0591x; 1.0554x over previous
#include <cuda_runtime.h>
#include <cstdint>
#include <math.h>

// Problem constants
#define Bq 128
#define Tq 2048
#define Dq 128
#define Hq 512
#define Lq 10

// Geometry: 128 persistent blocks = 4 batch-tiles (BT=32) x 32 j-tiles (JT=16)
#define NBLK 128
#define NTHREADS 256
#define BT 32
#define JT 16
#define CC 64            // output cols per block = 4 gates x JT
#define KIN 640          // H + D
#define KCH 160          // A chunk length (4 chunks)
#define NCH 4

// Shared memory (floats)
#define SM_W   (KIN*CC)        // 40960 : resident weights [k][col]
#define SM_A   (BT*KCH)        // 5120  : one A chunk [b][kchunk]
#define SM_G   (BT*CC)         // 2048  : gates staging
#define SM_C   (BT*JT)         // 512   : cell state
#define SM_TOTAL (SM_W + 2*SM_A + SM_G + SM_C)   // 53760 floats = 215040 B

__device__ float g_h[2][Bq * Hq];        // double-buffered hidden state
__device__ float g_Wt[32 * KIN * CC];    // reordered weights: [jt][k][col]
__device__ unsigned g_bar;               // monotonic grid barrier

typedef unsigned long long ull;

// ---------------------------------------------------------------------------
__global__ void init_kernel(const float* __restrict__ W_ih,
                            const float* __restrict__ W_hh) {
    unsigned idx = blockIdx.x * blockDim.x + threadIdx.x;
    unsigned stride = gridDim.x * blockDim.x;
    if (idx == 0) g_bar = 0u;
    for (unsigned i = idx; i < Bq * Hq; i += stride) g_h[0][i] = 0.f;

    const unsigned total = 32u * KIN * CC;
    for (unsigned i = idx; i < total; i += stride) {
        unsigned jt  = i / (KIN * CC);
        unsigned r   = i - jt * (KIN * CC);
        unsigned k   = r / CC;
        unsigned col = r - k * CC;
        unsigned gate = col >> 4, jj = col & 15u;
        unsigned row = gate * Hq + jt * JT + jj;
        g_Wt[i] = (k < Hq) ? W_hh[row * Hq + k]
                           : W_ih[row * Dq + (k - Hq)];
    }
}

__device__ __forceinline__ unsigned smem_u32(const void* p) {
    return (unsigned)__cvta_generic_to_shared(p);
}
__device__ __forceinline__ void ffma2(ull& d, ull a, ull b) {
    asm("fma.rn.f32x2 %0, %1, %2, %0;" : "+l"(d) : "l"(a), "l"(b));
}
__device__ __forceinline__ ull splat2(float v) {
    ull r; asm("mov.b64 %0, {%1, %1};" : "=l"(r) : "f"(v)); return r;
}
__device__ __forceinline__ ull pack2(float lo, float hi) {
    ull r; asm("mov.b64 %0, {%1, %2};" : "=l"(r) : "f"(lo), "f"(hi)); return r;
}
__device__ __forceinline__ void unpack2(ull v, float& lo, float& hi) {
    asm("mov.b64 {%0, %1}, %2;" : "=f"(lo), "=f"(hi) : "l"(v));
}
__device__ __forceinline__ float sigm(float v) {
    return 1.f / (1.f + __expf(-v));
}
__device__ __forceinline__ float tanh_fast(float v) {
    return 1.f - 2.f / (__expf(2.f * v) + 1.f);
}

// Load one A chunk [32 rows x 160 k] via cp.async (16B granules).
// chunk c covers kglobal [c*160, c*160+160): c<3 all h; c==3: 32 h + 128 x.
__device__ __forceinline__ void loadA(float* dst, int c, const float* hin,
                                      const float* x, int t, int bbase, int tid) {
    unsigned s = smem_u32(dst);
#pragma unroll
    for (int i = 0; i < 5; i++) {
        int q = tid + i * NTHREADS;        // 0..1279 (row*40 + f4)
        int row = q / 40;
        int f4 = q - row * 40;
        const float* src;
        if (c < 3)
            src = hin + (bbase + row) * Hq + c * KCH + f4 * 4;
        else if (f4 < 8)
            src = hin + (bbase + row) * Hq + 480 + f4 * 4;
        else
            src = x + ((size_t)(bbase + row) * Tq + t) * Dq + (f4 - 8) * 4;
        asm volatile("cp.async.cg.shared.global [%0], [%1], 16;\n"
                     :: "r"(s + q * 16), "l"(src) : "memory");
    }
    asm volatile("cp.async.commit_group;\n" ::: "memory");
}

// ---------------------------------------------------------------------------
__global__ __launch_bounds__(NTHREADS, 1)
void lstm_kernel(const float* __restrict__ x,
                 const float* __restrict__ bias,
                 const float* __restrict__ Wout,
                 float* __restrict__ out) {
    extern __shared__ float sm[];
    float* Wsh = sm;                 // [640][64]
    float* ab0 = Wsh + SM_W;         // [32][160]
    float* ab1 = ab0 + SM_A;
    float* gsh = ab1 + SM_A;         // [32][64]
    float* csh = gsh + SM_G;         // [32][16]

    const int tid  = threadIdx.x;
    const int bt   = blockIdx.x >> 5;          // 4 batch tiles
    const int jt   = blockIdx.x & 31;          // 32 j tiles
    const int lane = tid & 31;
    const int w    = tid >> 5;
    const int cg   = w & 1;
    const int rg   = w >> 1;
    const int cl   = cg * 32 + (lane & 7) * 4; // 4 output cols
    const int r0   = rg * 8 + (lane >> 3) * 2; // 2 batch rows
    const int bbase = bt * BT;

    // Load resident W tile (once)
    {
        const float4* src = (const float4*)(g_Wt + (size_t)jt * (KIN * CC));
        float4* dst = (float4*)Wsh;
#pragma unroll 4
        for (int i = tid; i < SM_W / 4; i += NTHREADS) dst[i] = src[i];
    }
    for (int i = tid; i < SM_C; i += NTHREADS) csh[i] = 0.f;

    // Packed bias for this thread's 4 cols
    ull bias01, bias23;
    {
        float bb[4];
#pragma unroll
        for (int i = 0; i < 4; i++) {
            int col = cl + i;
            int gate = col >> 4, jj = col & 15;
            bb[i] = bias[gate * Hq + jt * JT + jj];
        }
        bias01 = pack2(bb[0], bb[1]);
        bias23 = pack2(bb[2], bb[3]);
    }
    __syncthreads();

    for (int t = 0; t < Tq; ++t) {
        const int p = t & 1;
        const float* __restrict__ hin = g_h[p];
        float* __restrict__ hout      = g_h[p ^ 1];

        loadA(ab0, 0, hin, x, t, bbase, tid);

        ull acc00 = bias01, acc01 = bias23;   // row r0
        ull acc10 = bias01, acc11 = bias23;   // row r0+1

#pragma unroll 1
        for (int c = 0; c < NCH; ++c) {
            asm volatile("cp.async.wait_group 0;\n" ::: "memory");
            __syncthreads();
            if (c < NCH - 1)
                loadA((c & 1) ? ab0 : ab1, c + 1, hin, x, t, bbase, tid);

            const float* ab = (c & 1) ? ab1 : ab0;
            const float* ap0 = ab + r0 * KCH;
            const float* ap1 = ap0 + KCH;
            const float* wp  = Wsh + c * KCH * CC + cl;

#pragma unroll 2
            for (int k4 = 0; k4 < KCH; k4 += 4) {
                float4 a0 = *(const float4*)(ap0 + k4);
                float4 a1 = *(const float4*)(ap1 + k4);
#pragma unroll
                for (int kk = 0; kk < 4; ++kk) {
                    ulonglong2 wv = *(const ulonglong2*)(wp + (k4 + kk) * CC);
                    float a0s = (kk == 0) ? a0.x : (kk == 1) ? a0.y : (kk == 2) ? a0.z : a0.w;
                    float a1s = (kk == 0) ? a1.x : (kk == 1) ? a1.y : (kk == 2) ? a1.z : a1.w;
                    ull s0 = splat2(a0s), s1 = splat2(a1s);
                    ffma2(acc00, s0, wv.x);
                    ffma2(acc01, s0, wv.y);
                    ffma2(acc10, s1, wv.x);
                    ffma2(acc11, s1, wv.y);
                }
            }
        }

        // Stage gates
        {
            float v0, v1, v2, v3;
            unpack2(acc00, v0, v1); unpack2(acc01, v2, v3);
            *(float4*)(gsh + r0 * CC + cl) = make_float4(v0, v1, v2, v3);
            unpack2(acc10, v0, v1); unpack2(acc11, v2, v3);
            *(float4*)(gsh + (r0 + 1) * CC + cl) = make_float4(v0, v1, v2, v3);
        }
        __syncthreads();

        // Elementwise LSTM update (2 cells per thread)
#pragma unroll
        for (int u = 0; u < 2; ++u) {
            int e = tid * 2 + u;           // 0..511
            int b = e >> 4, jj = e & 15;
            const float* gr = gsh + b * CC;
            float iS = sigm(gr[jj]);
            float fS = sigm(gr[16 + jj]);
            float gT = tanh_fast(gr[32 + jj]);
            float oS = sigm(gr[48 + jj]);
            float cn = fS * csh[e] + iS * gT;
            csh[e] = cn;
            hout[(bbase + b) * Hq + jt * JT + jj] = oS * tanh_fast(cn);
        }

        // Grid barrier (128 co-resident blocks)
        __threadfence();
        __syncthreads();
        if (tid == 0) {
            atomicAdd(&g_bar, 1u);
            unsigned target = (unsigned)(t + 1) * (unsigned)NBLK;
            while (*((volatile unsigned*)&g_bar) < target) { }
        }
        __syncthreads();
    }

    // Output head: jt==0 blocks do logits + softmax for their 32 batch rows.
    if (jt == 0) {
        for (int i = tid; i < BT * Hq; i += NTHREADS) {
            int b = i >> 9, k = i & (Hq - 1);
            Wsh[b * Hq + k] = g_h[0][(bbase + b) * Hq + k];
        }
        __syncthreads();
        for (int q = tid; q < BT * Lq; q += NTHREADS) {
            int b = q / Lq, l = q - b * Lq;
            const float* hr = Wsh + b * Hq;
            const float* wr = Wout + l * Hq;
            float s = 0.f;
            for (int k = 0; k < Hq; k++) s += hr[k] * wr[k];
            gsh[b * Lq + l] = s;
        }
        __syncthreads();
        if (tid < BT) {
            int b = tid;
            float m = -1e30f;
            for (int l = 0; l < Lq; l++) m = fmaxf(m, gsh[b * Lq + l]);
            float e[Lq]; float ssum = 0.f;
            for (int l = 0; l < Lq; l++) { e[l] = expf(gsh[b * Lq + l] - m); ssum += e[l]; }
            float inv = 1.f / ssum;
            for (int l = 0; l < Lq; l++) out[(bbase + b) * Lq + l] = e[l] * inv;
        }
    }
}

extern "C" void kernel_launch(void* const* d_in, const int* in_sizes, int n_in,
                              void* d_out, int out_size) {
    const float* x     = (const float*)d_in[0];
    const float* W_ih  = (const float*)d_in[1];
    const float* W_hh  = (const float*)d_in[2];
    const float* b     = (const float*)d_in[3];
    const float* W_out = (const float*)d_in[4];
    float* out = (float*)d_out;

    cudaFuncSetAttribute(lstm_kernel,
                         cudaFuncAttributeMaxDynamicSharedMemorySize,
                         SM_TOTAL * (int)sizeof(float));

    init_kernel<<<256, 256>>>(W_ih, W_hh);
    lstm_kernel<<<NBLK, NTHREADS, SM_TOTAL * (int)sizeof(float)>>>(x, b, W_out, out);
}

// round 9
// speedup vs baseline: 2.2131x; 2.0896x over previous
#include <cuda_runtime.h>
#include <cuda_bf16.h>
#include <cstdint>
#include <math.h>

// Problem constants
#define Bq 128
#define Tq 2048
#define Dq 128
#define Hq 512
#define Lq 10

// Geometry: 128 persistent blocks = 4 batch-tiles (M=32) x 32 col-tiles (N=64)
#define NBLK 128
#define NT 128            // 4 warps: wk = wid&1 (k parity), wn = wid>>1 (n half)
#define KTOT 640          // H + D
#define KC 160            // k per A chunk
#define NCHK 4

// Strides (bf16 elements) with bank-conflict-avoiding padding
#define WPAD 648          // W row stride   (1296B, phase-conflict-free for ldmatrix)
#define APAD 168          // A row stride   (336B)
#define GPAD 66           // gates partial row stride (floats)

// Shared memory byte offsets
#define OFF_W   0                         // [sel][64][WPAD] bf16 : 165888
#define W_SEL   (64*WPAD*2)               // 82944
#define OFF_A   165888                    // 2 slots x [sel][32][APAD] bf16
#define A_SLOT  (2*32*APAD*2)             // 21504
#define A_SEL   (32*APAD*2)               // 10752
#define OFF_G   208896                    // 2 x [32][GPAD] f32 : 16896
#define G_SEL   (32*GPAD*4)               // 8448
#define SMEM_BYTES (225792 + 1024)

typedef unsigned short u16;
typedef unsigned int u32;

// Device scratch
__device__ u16 g_Ahi[2][Bq * KTOT];     // A = [h | x_t] bf16-hi, double-buffered
__device__ u16 g_Alo[2][Bq * KTOT];     // bf16-lo residual
__device__ u16 g_Wb[32][2 * 64 * WPAD]; // per-ntile W tiles [sel][n][k], padded
__device__ unsigned g_bar;

// ---------------------------------------------------------------------------
__device__ __forceinline__ void split_bf16(float v, u16& hi, u16& lo) {
    __nv_bfloat16 h = __float2bfloat16_rn(v);
    hi = __bfloat16_as_ushort(h);
    lo = __bfloat16_as_ushort(__float2bfloat16_rn(v - __bfloat162float(h)));
}

__global__ void init_kernel(const float* __restrict__ x,
                            const float* __restrict__ W_ih,
                            const float* __restrict__ W_hh) {
    unsigned idx = blockIdx.x * blockDim.x + threadIdx.x;
    unsigned stride = gridDim.x * blockDim.x;
    if (idx == 0) g_bar = 0u;

    for (unsigned i = idx; i < Bq * Hq; i += stride) {
        unsigned b = i >> 9, k = i & 511u;
        g_Ahi[0][b * KTOT + k] = 0; g_Alo[0][b * KTOT + k] = 0;
    }
    for (unsigned i = idx; i < Bq * Dq; i += stride) {
        unsigned b = i >> 7, d = i & 127u;
        u16 hi, lo; split_bf16(x[((size_t)b * Tq) * Dq + d], hi, lo);
        g_Ahi[0][b * KTOT + Hq + d] = hi;
        g_Alo[0][b * KTOT + Hq + d] = lo;
    }
    // W tiles: nt tile owns gate cols n = gate*16 + jl -> W row gate*512 + nt*16 + jl
    const unsigned total = 32u * 64u * KTOT;
    for (unsigned i = idx; i < total; i += stride) {
        unsigned nt = i / (64 * KTOT);
        unsigned r = i - nt * (64 * KTOT);
        unsigned n = r / KTOT, k = r - n * KTOT;
        unsigned row = (n >> 4) * Hq + nt * 16 + (n & 15u);
        float w = (k < Hq) ? W_hh[row * Hq + k] : W_ih[row * Dq + (k - Hq)];
        u16 hi, lo; split_bf16(w, hi, lo);
        g_Wb[nt][n * WPAD + k] = hi;
        g_Wb[nt][64 * WPAD + n * WPAD + k] = lo;
    }
}

// ---------------------------------------------------------------------------
__device__ __forceinline__ void ldsm4(u32* r, unsigned addr) {
    asm volatile("ldmatrix.sync.aligned.m8n8.x4.shared.b16 {%0,%1,%2,%3}, [%4];"
                 : "=r"(r[0]), "=r"(r[1]), "=r"(r[2]), "=r"(r[3]) : "r"(addr));
}
__device__ __forceinline__ void mma16816(float* d, const u32* a, const u32* b) {
    asm volatile(
        "mma.sync.aligned.m16n8k16.row.col.f32.bf16.bf16.f32 "
        "{%0,%1,%2,%3}, {%4,%5,%6,%7}, {%8,%9}, {%0,%1,%2,%3};"
        : "+f"(d[0]), "+f"(d[1]), "+f"(d[2]), "+f"(d[3])
        : "r"(a[0]), "r"(a[1]), "r"(a[2]), "r"(a[3]), "r"(b[0]), "r"(b[1]));
}
__device__ __forceinline__ float sigm(float v) { return 1.f / (1.f + __expf(-v)); }
__device__ __forceinline__ float tanh_fast(float v) { return 1.f - 2.f / (__expf(2.f * v) + 1.f); }

// Copy one A chunk (hi+lo, 20.5KB) into a slot. 128 threads, 10 cp.async each.
__device__ __forceinline__ void copy_chunk(unsigned smb, int slot, int c,
                                           const u16* Ah, const u16* Al,
                                           int bbase, int tid) {
    unsigned base = smb + OFF_A + slot * A_SLOT;
    int row = tid >> 2, qq = tid & 3;
    const u16* sh = Ah + (size_t)(bbase + row) * KTOT + c * KC;
    const u16* sl = Al + (size_t)(bbase + row) * KTOT + c * KC;
    unsigned d = base + row * (APAD * 2);
#pragma unroll
    for (int j = 0; j < 5; j++) {
        int kg = qq * 5 + j;   // 16B granule (8 bf16)
        asm volatile("cp.async.cg.shared.global [%0], [%1], 16;\n"
                     :: "r"(d + kg * 16), "l"(sh + kg * 8) : "memory");
        asm volatile("cp.async.cg.shared.global [%0], [%1], 16;\n"
                     :: "r"(d + A_SEL + kg * 16), "l"(sl + kg * 8) : "memory");
    }
    asm volatile("cp.async.commit_group;\n" ::: "memory");
}

// ---------------------------------------------------------------------------
__global__ __launch_bounds__(NT, 1)
void lstm_kernel(const float* __restrict__ x,
                 const float* __restrict__ bias,
                 const float* __restrict__ Wout,
                 float* __restrict__ out) {
    extern __shared__ char smraw[];
    char* sm = (char*)(((uintptr_t)smraw + 1023) & ~(uintptr_t)1023);
    unsigned smb = (unsigned)__cvta_generic_to_shared(sm);

    const int tid = threadIdx.x;
    const int lane = tid & 31;
    const int wid = tid >> 5;
    const int wk = wid & 1;          // k-step parity this warp handles
    const int wn = wid >> 1;         // n half (32 cols)
    const int blk = blockIdx.x;
    const int bt = blk >> 5, nt = blk & 31;
    const int bbase = bt * 32;

    // Load resident W tile (165888B, shared by 4 blocks with same nt)
    {
        const u16* src = g_Wb[nt];
#pragma unroll 1
        for (int i = tid; i < (2 * 64 * WPAD) / 8; i += NT) {
            asm volatile("cp.async.cg.shared.global [%0], [%1], 16;\n"
                         :: "r"(smb + OFF_W + i * 16), "l"(src + i * 8) : "memory");
        }
        asm volatile("cp.async.commit_group;\n" ::: "memory");
    }

    // ldmatrix per-lane offsets
    const unsigned a_off = (lane & 15) * (APAD * 2) + (lane >> 4) * 16;
    const unsigned w_row = (lane & 7) | ((lane >> 4) << 3);
    const unsigned w_half = ((lane >> 3) & 1) * 16;
    // W bases for the 2 n16 tiles of this warp, hi and lo
    unsigned wb_hi0 = smb + OFF_W + (wn * 32 + 0  + w_row) * (WPAD * 2) + w_half;
    unsigned wb_hi1 = smb + OFF_W + (wn * 32 + 16 + w_row) * (WPAD * 2) + w_half;
    unsigned wb_lo0 = wb_hi0 + W_SEL;
    unsigned wb_lo1 = wb_hi1 + W_SEL;

    // Bias + cell state in registers: cell e = q*128+tid -> b = e>>4, jj = e&15
    float bias_r[4][4], creg[4];
#pragma unroll
    for (int q = 0; q < 4; q++) {
        int jj = ((q * NT + tid) & 15);
#pragma unroll
        for (int g = 0; g < 4; g++)
            bias_r[q][g] = bias[g * Hq + nt * 16 + jj];
        creg[q] = 0.f;
    }

    asm volatile("cp.async.wait_group 0;\n" ::: "memory");
    __syncthreads();

    float* gp0 = (float*)(sm + OFF_G);
    float* gp1 = (float*)(sm + OFF_G + G_SEL);
    float* gpw = wk ? gp1 : gp0;

#pragma unroll 1
    for (int t = 0; t < Tq; ++t) {
        const int p = t & 1;
        const u16* Ah = g_Ahi[p];
        const u16* Al = g_Alo[p];

        copy_chunk(smb, 0, 0, Ah, Al, bbase, tid);
        copy_chunk(smb, 1, 1, Ah, Al, bbase, tid);

        float acc[8][4];   // [mt*4 + ntile*2 + nsub][4]
#pragma unroll
        for (int i = 0; i < 8; i++)
#pragma unroll
            for (int j = 0; j < 4; j++) acc[i][j] = 0.f;

#pragma unroll 1
        for (int c = 0; c < NCHK; ++c) {
            if (c < NCHK - 1) asm volatile("cp.async.wait_group 1;\n" ::: "memory");
            else              asm volatile("cp.async.wait_group 0;\n" ::: "memory");
            __syncthreads();

            const unsigned abase_hi = smb + OFF_A + (c & 1) * A_SLOT + a_off;
            const unsigned abase_lo = abase_hi + A_SEL;
            const unsigned kb2 = (unsigned)(c * KC) * 2;

#pragma unroll
            for (int s = 0; s < 5; s++) {
                const int ks = 2 * s + wk;
                const unsigned ka = (unsigned)ks * 32;
                u32 ah0[4], ah1[4], al0[4], al1[4];
                ldsm4(ah0, abase_hi + ka);
                ldsm4(ah1, abase_hi + 16 * (APAD * 2) + ka);
                ldsm4(al0, abase_lo + ka);
                ldsm4(al1, abase_lo + 16 * (APAD * 2) + ka);
                u32 wh0[4], wh1[4], wl0[4], wl1[4];
                const unsigned kw = kb2 + ka;
                ldsm4(wh0, wb_hi0 + kw);
                ldsm4(wl0, wb_lo0 + kw);
                ldsm4(wh1, wb_hi1 + kw);
                ldsm4(wl1, wb_lo1 + kw);
                // hh + hl + lh, 2 m-tiles x 2 n16-tiles x 2 n8-subs
                mma16816(acc[0], ah0, wh0);     mma16816(acc[1], ah0, wh0 + 2);
                mma16816(acc[2], ah0, wh1);     mma16816(acc[3], ah0, wh1 + 2);
                mma16816(acc[4], ah1, wh0);     mma16816(acc[5], ah1, wh0 + 2);
                mma16816(acc[6], ah1, wh1);     mma16816(acc[7], ah1, wh1 + 2);
                mma16816(acc[0], ah0, wl0);     mma16816(acc[1], ah0, wl0 + 2);
                mma16816(acc[2], ah0, wl1);     mma16816(acc[3], ah0, wl1 + 2);
                mma16816(acc[4], ah1, wl0);     mma16816(acc[5], ah1, wl0 + 2);
                mma16816(acc[6], ah1, wl1);     mma16816(acc[7], ah1, wl1 + 2);
                mma16816(acc[0], al0, wh0);     mma16816(acc[1], al0, wh0 + 2);
                mma16816(acc[2], al0, wh1);     mma16816(acc[3], al0, wh1 + 2);
                mma16816(acc[4], al1, wh0);     mma16816(acc[5], al1, wh0 + 2);
                mma16816(acc[6], al1, wh1);     mma16816(acc[7], al1, wh1 + 2);
            }
            __syncthreads();
            if (c + 2 < NCHK)
                copy_chunk(smb, c & 1, c + 2, Ah, Al, bbase, tid);
        }

        // Stage per-warp-k partial gates: gpw[m][col]
#pragma unroll
        for (int mt = 0; mt < 2; mt++)
#pragma unroll
            for (int ntile = 0; ntile < 2; ntile++)
#pragma unroll
                for (int nsub = 0; nsub < 2; nsub++) {
                    const float* a4 = acc[mt * 4 + ntile * 2 + nsub];
                    int m = mt * 16 + (lane >> 2);
                    int col = wn * 32 + ntile * 16 + nsub * 8 + (lane & 3) * 2;
                    *(float2*)&gpw[m * GPAD + col] = make_float2(a4[0], a4[1]);
                    *(float2*)&gpw[(m + 8) * GPAD + col] = make_float2(a4[2], a4[3]);
                }

        // x conversion for step t+1 (overlaps with gates staging of other warps)
        if (t + 1 < Tq) {
            float v = x[((size_t)blk * Tq + (t + 1)) * Dq + tid];
            u16 hi, lo; split_bf16(v, hi, lo);
            g_Ahi[p ^ 1][blk * KTOT + Hq + tid] = hi;
            g_Alo[p ^ 1][blk * KTOT + Hq + tid] = lo;
        }
        __syncthreads();

        // Elementwise LSTM update: 4 cells per thread, c in registers
#pragma unroll
        for (int q = 0; q < 4; q++) {
            int e = q * NT + tid;
            int b = e >> 4, jj = e & 15;
            int gb = b * GPAD + jj;
            float gi = gp0[gb]      + gp1[gb]      + bias_r[q][0];
            float gf = gp0[gb + 16] + gp1[gb + 16] + bias_r[q][1];
            float gg = gp0[gb + 32] + gp1[gb + 32] + bias_r[q][2];
            float go = gp0[gb + 48] + gp1[gb + 48] + bias_r[q][3];
            float cn = sigm(gf) * creg[q] + sigm(gi) * tanh_fast(gg);
            creg[q] = cn;
            float h = sigm(go) * tanh_fast(cn);
            u16 hi, lo; split_bf16(h, hi, lo);
            size_t gidx = (size_t)(bbase + b) * KTOT + nt * 16 + jj;
            g_Ahi[p ^ 1][gidx] = hi;
            g_Alo[p ^ 1][gidx] = lo;
        }

        // Grid barrier (128 co-resident blocks)
        __threadfence();
        __syncthreads();
        if (tid == 0) {
            atomicAdd(&g_bar, 1u);
            unsigned target = (unsigned)(t + 1) * (unsigned)NBLK;
            while (*((volatile unsigned*)&g_bar) < target) { }
        }
        __syncthreads();
    }

    // Output head: blocks 0..3, 32 batch rows each. Final h at parity 0.
    if (blk < 4) {
        float* hst = (float*)sm;            // 32x512 fp32 staging (over W region)
        float* lst = hst + 32 * Hq;
        const int rbase = blk * 32;
        __syncthreads();
        for (int i = tid; i < 32 * Hq; i += NT) {
            int b = i >> 9, k = i & 511;
            size_t gi = (size_t)(rbase + b) * KTOT + k;
            hst[i] = __bfloat162float(__ushort_as_bfloat16(g_Ahi[0][gi])) +
                     __bfloat162float(__ushort_as_bfloat16(g_Alo[0][gi]));
        }
        __syncthreads();
        for (int q = tid; q < 32 * Lq; q += NT) {
            int b = q / Lq, l = q - b * Lq;
            const float* hr = hst + b * Hq;
            const float* wr = Wout + l * Hq;
            float s = 0.f;
            for (int k = 0; k < Hq; k++) s += hr[k] * wr[k];
            lst[q] = s;
        }
        __syncthreads();
        if (tid < 32) {
            int b = tid;
            float m = -1e30f;
            for (int l = 0; l < Lq; l++) m = fmaxf(m, lst[b * Lq + l]);
            float e[Lq]; float ssum = 0.f;
            for (int l = 0; l < Lq; l++) { e[l] = expf(lst[b * Lq + l] - m); ssum += e[l]; }
            float inv = 1.f / ssum;
            for (int l = 0; l < Lq; l++) out[(rbase + b) * Lq + l] = e[l] * inv;
        }
    }
}

extern "C" void kernel_launch(void* const* d_in, const int* in_sizes, int n_in,
                              void* d_out, int out_size) {
    const float* x     = (const float*)d_in[0];
    const float* W_ih  = (const float*)d_in[1];
    const float* W_hh  = (const float*)d_in[2];
    const float* b     = (const float*)d_in[3];
    const float* W_out = (const float*)d_in[4];
    float* out = (float*)d_out;

    cudaFuncSetAttribute(lstm_kernel,
                         cudaFuncAttributeMaxDynamicSharedMemorySize, SMEM_BYTES);

    init_kernel<<<256, 256>>>(x, W_ih, W_hh);
    lstm_kernel<<<NBLK, NT, SMEM_BYTES>>>(x, b, W_out, out);
}

// round 11
// speedup vs baseline: 2.8262x; 1.2770x over previous
#include <cuda_runtime.h>
#include <cuda_bf16.h>
#include <cstdint>
#include <math.h>

// Problem constants
#define Bq 128
#define Tq 2048
#define Dq 128
#define Hq 512
#define Lq 10

// Geometry: 128 persistent blocks = 4 batch-groups (bt) x 32 col-tiles (nt)
// Block: M=32 batch rows, N=64 gate cols. 8 warps: wk=wid&1 (k parity),
// wn=wid>>1 (16-col n-tile).
#define NBLK 128
#define NT 256
#define KTOT 640
#define KC 128
#define NCHK 5

// Padded strides (conflict-free ldmatrix: byte stride = odd multiple of 16)
#define WPAD 648          // bf16; 1296B
#define APAD 136          // bf16; 272B
#define GPAD 66           // floats

// Shared memory layout (bytes)
#define OFF_W   0
#define W_SEL   (64*WPAD*2)               // 82944 (hi->lo)
#define OFF_A   165888
#define A_SEL   (32*APAD*2)               // 8704 (hi->lo within slot)
#define A_SLOT  (2*A_SEL)                 // 17408
#define OFF_G   (OFF_A + 2*A_SLOT)        // 200704
#define G_SEL   (32*GPAD*4)               // 8448
#define SMEM_BYTES (OFF_G + 2*G_SEL + 1024)

typedef unsigned short u16;
typedef unsigned int u32;

__device__ u16 g_Ahi[2][Bq * KTOT];
__device__ u16 g_Alo[2][Bq * KTOT];
__device__ u16 g_Wb[32][2 * 64 * WPAD];
__device__ unsigned g_bar4[4 * 32];       // per-bt barrier, 128B apart

// ---------------------------------------------------------------------------
__device__ __forceinline__ void split_bf16(float v, u16& hi, u16& lo) {
    __nv_bfloat16 h = __float2bfloat16_rn(v);
    hi = __bfloat16_as_ushort(h);
    lo = __bfloat16_as_ushort(__float2bfloat16_rn(v - __bfloat162float(h)));
}

__global__ void init_kernel(const float* __restrict__ x,
                            const float* __restrict__ W_ih,
                            const float* __restrict__ W_hh) {
    unsigned idx = blockIdx.x * blockDim.x + threadIdx.x;
    unsigned stride = gridDim.x * blockDim.x;
    if (idx < 4) g_bar4[idx * 32] = 0u;

    for (unsigned i = idx; i < Bq * Hq; i += stride) {
        unsigned b = i >> 9, k = i & 511u;
        g_Ahi[0][b * KTOT + k] = 0; g_Alo[0][b * KTOT + k] = 0;
    }
    for (unsigned i = idx; i < Bq * Dq; i += stride) {
        unsigned b = i >> 7, d = i & 127u;
        u16 hi, lo; split_bf16(x[((size_t)b * Tq) * Dq + d], hi, lo);
        g_Ahi[0][b * KTOT + Hq + d] = hi;
        g_Alo[0][b * KTOT + Hq + d] = lo;
    }
    const unsigned total = 32u * 64u * KTOT;
    for (unsigned i = idx; i < total; i += stride) {
        unsigned nt = i / (64 * KTOT);
        unsigned r = i - nt * (64 * KTOT);
        unsigned n = r / KTOT, k = r - n * KTOT;
        unsigned row = (n >> 4) * Hq + nt * 16 + (n & 15u);
        float w = (k < Hq) ? W_hh[row * Hq + k] : W_ih[row * Dq + (k - Hq)];
        u16 hi, lo; split_bf16(w, hi, lo);
        g_Wb[nt][n * WPAD + k] = hi;
        g_Wb[nt][64 * WPAD + n * WPAD + k] = lo;
    }
}

// ---------------------------------------------------------------------------
__device__ __forceinline__ void ldsm4(u32* r, unsigned addr) {
    asm volatile("ldmatrix.sync.aligned.m8n8.x4.shared.b16 {%0,%1,%2,%3}, [%4];"
                 : "=r"(r[0]), "=r"(r[1]), "=r"(r[2]), "=r"(r[3]) : "r"(addr));
}
__device__ __forceinline__ void mma16816(float* d, const u32* a, const u32* b) {
    asm volatile(
        "mma.sync.aligned.m16n8k16.row.col.f32.bf16.bf16.f32 "
        "{%0,%1,%2,%3}, {%4,%5,%6,%7}, {%8,%9}, {%0,%1,%2,%3};"
        : "+f"(d[0]), "+f"(d[1]), "+f"(d[2]), "+f"(d[3])
        : "r"(a[0]), "r"(a[1]), "r"(a[2]), "r"(a[3]), "r"(b[0]), "r"(b[1]));
}
__device__ __forceinline__ float sigm(float v) { return 1.f / (1.f + __expf(-v)); }
__device__ __forceinline__ float tanh_fast(float v) { return 1.f - 2.f / (__expf(2.f * v) + 1.f); }

// Copy one A chunk (hi+lo, 16KB data) into a slot. 256 threads x 4 cp.async.
__device__ __forceinline__ void copy_chunk(unsigned smb, int slot, int c,
                                           const u16* Ah, const u16* Al,
                                           int bbase, int tid) {
    unsigned base = smb + OFF_A + slot * A_SLOT;
    int row = tid >> 3, kgb = (tid & 7) * 2;      // 2 16B granules per sel
    const u16* sh = Ah + (size_t)(bbase + row) * KTOT + c * KC + kgb * 8;
    const u16* sl = Al + (size_t)(bbase + row) * KTOT + c * KC + kgb * 8;
    unsigned d = base + row * (APAD * 2) + kgb * 16;
    asm volatile("cp.async.cg.shared.global [%0], [%1], 16;\n" :: "r"(d), "l"(sh) : "memory");
    asm volatile("cp.async.cg.shared.global [%0], [%1], 16;\n" :: "r"(d + 16), "l"(sh + 8) : "memory");
    asm volatile("cp.async.cg.shared.global [%0], [%1], 16;\n" :: "r"(d + A_SEL), "l"(sl) : "memory");
    asm volatile("cp.async.cg.shared.global [%0], [%1], 16;\n" :: "r"(d + A_SEL + 16), "l"(sl + 8) : "memory");
    asm volatile("cp.async.commit_group;\n" ::: "memory");
}

// ---------------------------------------------------------------------------
__global__ __launch_bounds__(NT, 1)
void lstm_kernel(const float* __restrict__ x,
                 const float* __restrict__ bias,
                 const float* __restrict__ Wout,
                 float* __restrict__ out) {
    extern __shared__ char smraw[];
    char* sm = (char*)(((uintptr_t)smraw + 1023) & ~(uintptr_t)1023);
    unsigned smb = (unsigned)__cvta_generic_to_shared(sm);

    const int tid = threadIdx.x;
    const int lane = tid & 31;
    const int wid = tid >> 5;
    const int wk = wid & 1;
    const int wn = wid >> 1;                  // 0..3
    const int blk = blockIdx.x;
    const int bt = blk >> 5, nt = blk & 31;
    const int bbase = bt * 32;
    volatile unsigned* barp = &g_bar4[bt * 32];

    // Load resident W tile
    {
        const u16* src = g_Wb[nt];
#pragma unroll 1
        for (int i = tid; i < (2 * 64 * WPAD) / 8; i += NT) {
            asm volatile("cp.async.cg.shared.global [%0], [%1], 16;\n"
                         :: "r"(smb + OFF_W + i * 16), "l"(src + i * 8) : "memory");
        }
        asm volatile("cp.async.commit_group;\n" ::: "memory");
    }

    const unsigned a_off = (lane & 15) * (APAD * 2) + (lane >> 4) * 16;
    const unsigned w_row = (lane & 7) | ((lane >> 4) << 3);
    const unsigned w_half = ((lane >> 3) & 1) * 16;
    const unsigned wb_hi = smb + OFF_W + (wn * 16 + w_row) * (WPAD * 2) + w_half;
    const unsigned wb_lo = wb_hi + W_SEL;

    // Bias + register cell state: cell e = q*NT + tid -> b = e>>4, jj = tid&15
    const int jj_e = tid & 15;
    float bias_r[4], creg[2];
#pragma unroll
    for (int g = 0; g < 4; g++) bias_r[g] = bias[g * Hq + nt * 16 + jj_e];
    creg[0] = 0.f; creg[1] = 0.f;

    asm volatile("cp.async.wait_group 0;\n" ::: "memory");
    __syncthreads();

    float* gp0 = (float*)(sm + OFF_G);
    float* gp1 = (float*)(sm + OFF_G + G_SEL);
    float* gpw = wk ? gp1 : gp0;

#pragma unroll 1
    for (int t = 0; t < Tq; ++t) {
        const int p = t & 1;
        const u16* Ah = g_Ahi[p];
        const u16* Al = g_Alo[p];

        copy_chunk(smb, 0, 0, Ah, Al, bbase, tid);
        copy_chunk(smb, 1, 1, Ah, Al, bbase, tid);

        float acc[4][4];   // [mt*2 + nsub][4]
#pragma unroll
        for (int i = 0; i < 4; i++)
#pragma unroll
            for (int j = 0; j < 4; j++) acc[i][j] = 0.f;

#pragma unroll 1
        for (int c = 0; c < NCHK; ++c) {
            if (c < NCHK - 1) asm volatile("cp.async.wait_group 1;\n" ::: "memory");
            else              asm volatile("cp.async.wait_group 0;\n" ::: "memory");
            __syncthreads();

            const unsigned abase_hi = smb + OFF_A + (c & 1) * A_SLOT + a_off;
            const unsigned abase_lo = abase_hi + A_SEL;
            const unsigned kb2 = (unsigned)c * 256;   // W byte offset of chunk

#pragma unroll
            for (int s = 0; s < 4; s++) {
                const unsigned ka = (unsigned)(2 * s + wk) * 32;
                u32 ah0[4], ah1[4], al0[4], al1[4], wh[4], wl[4];
                ldsm4(ah0, abase_hi + ka);
                ldsm4(ah1, abase_hi + 16 * (APAD * 2) + ka);
                ldsm4(al0, abase_lo + ka);
                ldsm4(al1, abase_lo + 16 * (APAD * 2) + ka);
                ldsm4(wh, wb_hi + kb2 + ka);
                ldsm4(wl, wb_lo + kb2 + ka);
                mma16816(acc[0], ah0, wh);  mma16816(acc[1], ah0, wh + 2);
                mma16816(acc[2], ah1, wh);  mma16816(acc[3], ah1, wh + 2);
                mma16816(acc[0], ah0, wl);  mma16816(acc[1], ah0, wl + 2);
                mma16816(acc[2], ah1, wl);  mma16816(acc[3], ah1, wl + 2);
                mma16816(acc[0], al0, wh);  mma16816(acc[1], al0, wh + 2);
                mma16816(acc[2], al1, wh);  mma16816(acc[3], al1, wh + 2);
            }
            __syncthreads();
            if (c + 2 < NCHK)
                copy_chunk(smb, c & 1, c + 2, Ah, Al, bbase, tid);
        }

        // Stage per-k-parity partial gates
#pragma unroll
        for (int mt = 0; mt < 2; mt++)
#pragma unroll
            for (int nsub = 0; nsub < 2; nsub++) {
                const float* a4 = acc[mt * 2 + nsub];
                int m = mt * 16 + (lane >> 2);
                int col = wn * 16 + nsub * 8 + (lane & 3) * 2;
                *(float2*)&gpw[m * GPAD + col] = make_float2(a4[0], a4[1]);
                *(float2*)&gpw[(m + 8) * GPAD + col] = make_float2(a4[2], a4[3]);
            }

        // x conversion for step t+1 (this block owns batch row `blk`)
        if (t + 1 < Tq && tid < Dq) {
            float v = x[((size_t)blk * Tq + (t + 1)) * Dq + tid];
            u16 hi, lo; split_bf16(v, hi, lo);
            g_Ahi[p ^ 1][blk * KTOT + Hq + tid] = hi;
            g_Alo[p ^ 1][blk * KTOT + Hq + tid] = lo;
        }
        __syncthreads();

        // Elementwise LSTM: 2 cells per thread (b = q*16 + tid>>4, jj = tid&15)
#pragma unroll
        for (int q = 0; q < 2; q++) {
            int b = q * 16 + (tid >> 4);
            int gb = b * GPAD + jj_e;
            float gi = gp0[gb]      + gp1[gb]      + bias_r[0];
            float gf = gp0[gb + 16] + gp1[gb + 16] + bias_r[1];
            float gg = gp0[gb + 32] + gp1[gb + 32] + bias_r[2];
            float go = gp0[gb + 48] + gp1[gb + 48] + bias_r[3];
            float cn = sigm(gf) * creg[q] + sigm(gi) * tanh_fast(gg);
            creg[q] = cn;
            float h = sigm(go) * tanh_fast(cn);
            u16 hi, lo; split_bf16(h, hi, lo);
            size_t gidx = (size_t)(bbase + b) * KTOT + nt * 16 + jj_e;
            g_Ahi[p ^ 1][gidx] = hi;
            g_Alo[p ^ 1][gidx] = lo;
        }

        // Per-bt-group barrier (32 blocks)
        __threadfence();
        __syncthreads();
        if (tid == 0) {
            atomicAdd((unsigned*)barp, 1u);
            unsigned target = (unsigned)(t + 1) * 32u;
            while (*barp < target) { }
        }
        __syncthreads();
    }

    // Output head: nt==0 block of each group handles its own 32 rows.
    if (nt == 0) {
        float* hst = (float*)sm;            // 32x512 fp32 (over W region)
        float* lst = hst + 32 * Hq;
        const int rbase = bbase;
        __syncthreads();
        for (int i = tid; i < 32 * Hq; i += NT) {
            int b = i >> 9, k = i & 511;
            size_t gi = (size_t)(rbase + b) * KTOT + k;
            hst[i] = __bfloat162float(__ushort_as_bfloat16(g_Ahi[0][gi])) +
                     __bfloat162float(__ushort_as_bfloat16(g_Alo[0][gi]));
        }
        __syncthreads();
        for (int q = tid; q < 32 * Lq; q += NT) {
            int b = q / Lq, l = q - b * Lq;
            const float* hr = hst + b * Hq;
            const float* wr = Wout + l * Hq;
            float s = 0.f;
            for (int k = 0; k < Hq; k++) s += hr[k] * wr[k];
            lst[q] = s;
        }
        __syncthreads();
        if (tid < 32) {
            int b = tid;
            float m = -1e30f;
            for (int l = 0; l < Lq; l++) m = fmaxf(m, lst[b * Lq + l]);
            float e[Lq]; float ssum = 0.f;
            for (int l = 0; l < Lq; l++) { e[l] = expf(lst[b * Lq + l] - m); ssum += e[l]; }
            float inv = 1.f / ssum;
            for (int l = 0; l < Lq; l++) out[(rbase + b) * Lq + l] = e[l] * inv;
        }
    }
}

extern "C" void kernel_launch(void* const* d_in, const int* in_sizes, int n_in,
                              void* d_out, int out_size) {
    const float* x     = (const float*)d_in[0];
    const float* W_ih  = (const float*)d_in[1];
    const float* W_hh  = (const float*)d_in[2];
    const float* b     = (const float*)d_in[3];
    const float* W_out = (const float*)d_in[4];
    float* out = (float*)d_out;

    cudaFuncSetAttribute(lstm_kernel,
                         cudaFuncAttributeMaxDynamicSharedMemorySize, SMEM_BYTES);

    init_kernel<<<256, 256>>>(x, W_ih, W_hh);
    lstm_kernel<<<NBLK, NT, SMEM_BYTES>>>(x, b, W_out, out);
}

// round 12
// speedup vs baseline: 2.8301x; 1.0014x over previous
#include <cuda_runtime.h>
#include <cuda_bf16.h>
#include <cstdint>
#include <math.h>

// Problem constants
#define Bq 128
#define Tq 2048
#define Dq 128
#define Hq 512
#define Lq 10

// Geometry: 128 persistent blocks = 4 batch-groups (bt) x 32 col-tiles (nt)
// Block: M=32 batch rows, N=64 gate cols. 8 warps: wk=wid&1 (k parity),
// wn=wid>>1 (16-col n-tile).
#define NBLK 128
#define NT 256
#define KTOT 640
#define KC 128
#define NCHK 5

// Padded strides (conflict-free ldmatrix: byte stride = odd multiple of 16)
#define WPAD 648          // bf16; 1296B
#define APAD 136          // bf16; 272B
#define GPAD 66           // floats

// Shared memory layout (bytes)
#define OFF_W   0
#define W_SEL   (64*WPAD*2)               // 82944 (hi->lo)
#define OFF_A   165888
#define A_SEL   (32*APAD*2)               // 8704 (hi->lo within slot)
#define A_SLOT  (2*A_SEL)                 // 17408
#define OFF_G   (OFF_A + 2*A_SLOT)        // 200704
#define G_SEL   (32*GPAD*4)               // 8448
#define SMEM_BYTES (OFF_G + 2*G_SEL + 1024)

typedef unsigned short u16;
typedef unsigned int u32;

__device__ u16 g_Ahi[2][Bq * KTOT];
__device__ u16 g_Alo[2][Bq * KTOT];
__device__ u16 g_Wb[32][2 * 64 * WPAD];
__device__ unsigned g_bar4[4 * 32];       // per-bt barrier, 128B apart

// ---------------------------------------------------------------------------
__device__ __forceinline__ void split_bf16(float v, u16& hi, u16& lo) {
    __nv_bfloat16 h = __float2bfloat16_rn(v);
    hi = __bfloat16_as_ushort(h);
    lo = __bfloat16_as_ushort(__float2bfloat16_rn(v - __bfloat162float(h)));
}

__global__ void init_kernel(const float* __restrict__ x,
                            const float* __restrict__ W_ih,
                            const float* __restrict__ W_hh) {
    unsigned idx = blockIdx.x * blockDim.x + threadIdx.x;
    unsigned stride = gridDim.x * blockDim.x;
    if (idx < 4) g_bar4[idx * 32] = 0u;

    for (unsigned i = idx; i < Bq * Hq; i += stride) {
        unsigned b = i >> 9, k = i & 511u;
        g_Ahi[0][b * KTOT + k] = 0; g_Alo[0][b * KTOT + k] = 0;
    }
    for (unsigned i = idx; i < Bq * Dq; i += stride) {
        unsigned b = i >> 7, d = i & 127u;
        u16 hi, lo; split_bf16(x[((size_t)b * Tq) * Dq + d], hi, lo);
        g_Ahi[0][b * KTOT + Hq + d] = hi;
        g_Alo[0][b * KTOT + Hq + d] = lo;
    }
    const unsigned total = 32u * 64u * KTOT;
    for (unsigned i = idx; i < total; i += stride) {
        unsigned nt = i / (64 * KTOT);
        unsigned r = i - nt * (64 * KTOT);
        unsigned n = r / KTOT, k = r - n * KTOT;
        unsigned row = (n >> 4) * Hq + nt * 16 + (n & 15u);
        float w = (k < Hq) ? W_hh[row * Hq + k] : W_ih[row * Dq + (k - Hq)];
        u16 hi, lo; split_bf16(w, hi, lo);
        g_Wb[nt][n * WPAD + k] = hi;
        g_Wb[nt][64 * WPAD + n * WPAD + k] = lo;
    }
}

// ---------------------------------------------------------------------------
__device__ __forceinline__ void ldsm4(u32* r, unsigned addr) {
    asm volatile("ldmatrix.sync.aligned.m8n8.x4.shared.b16 {%0,%1,%2,%3}, [%4];"
                 : "=r"(r[0]), "=r"(r[1]), "=r"(r[2]), "=r"(r[3]) : "r"(addr));
}
__device__ __forceinline__ void mma16816(float* d, const u32* a, const u32* b) {
    asm volatile(
        "mma.sync.aligned.m16n8k16.row.col.f32.bf16.bf16.f32 "
        "{%0,%1,%2,%3}, {%4,%5,%6,%7}, {%8,%9}, {%0,%1,%2,%3};"
        : "+f"(d[0]), "+f"(d[1]), "+f"(d[2]), "+f"(d[3])
        : "r"(a[0]), "r"(a[1]), "r"(a[2]), "r"(a[3]), "r"(b[0]), "r"(b[1]));
}
__device__ __forceinline__ float sigm(float v) { return 1.f / (1.f + __expf(-v)); }
__device__ __forceinline__ float tanh_fast(float v) { return 1.f - 2.f / (__expf(2.f * v) + 1.f); }

// Copy one A chunk (hi+lo, 16KB data) into a slot. 256 threads x 4 cp.async.
__device__ __forceinline__ void copy_chunk(unsigned smb, int slot, int c,
                                           const u16* Ah, const u16* Al,
                                           int bbase, int tid) {
    unsigned base = smb + OFF_A + slot * A_SLOT;
    int row = tid >> 3, kgb = (tid & 7) * 2;      // 2 16B granules per sel
    const u16* sh = Ah + (size_t)(bbase + row) * KTOT + c * KC + kgb * 8;
    const u16* sl = Al + (size_t)(bbase + row) * KTOT + c * KC + kgb * 8;
    unsigned d = base + row * (APAD * 2) + kgb * 16;
    asm volatile("cp.async.cg.shared.global [%0], [%1], 16;\n" :: "r"(d), "l"(sh) : "memory");
    asm volatile("cp.async.cg.shared.global [%0], [%1], 16;\n" :: "r"(d + 16), "l"(sh + 8) : "memory");
    asm volatile("cp.async.cg.shared.global [%0], [%1], 16;\n" :: "r"(d + A_SEL), "l"(sl) : "memory");
    asm volatile("cp.async.cg.shared.global [%0], [%1], 16;\n" :: "r"(d + A_SEL + 16), "l"(sl + 8) : "memory");
    asm volatile("cp.async.commit_group;\n" ::: "memory");
}

// ---------------------------------------------------------------------------
__global__ __launch_bounds__(NT, 1)
void lstm_kernel(const float* __restrict__ x,
                 const float* __restrict__ bias,
                 const float* __restrict__ Wout,
                 float* __restrict__ out) {
    extern __shared__ char smraw[];
    char* sm = (char*)(((uintptr_t)smraw + 1023) & ~(uintptr_t)1023);
    unsigned smb = (unsigned)__cvta_generic_to_shared(sm);

    const int tid = threadIdx.x;
    const int lane = tid & 31;
    const int wid = tid >> 5;
    const int wk = wid & 1;
    const int wn = wid >> 1;                  // 0..3
    const int blk = blockIdx.x;
    const int bt = blk >> 5, nt = blk & 31;
    const int bbase = bt * 32;
    volatile unsigned* barp = &g_bar4[bt * 32];

    // Load resident W tile
    {
        const u16* src = g_Wb[nt];
#pragma unroll 1
        for (int i = tid; i < (2 * 64 * WPAD) / 8; i += NT) {
            asm volatile("cp.async.cg.shared.global [%0], [%1], 16;\n"
                         :: "r"(smb + OFF_W + i * 16), "l"(src + i * 8) : "memory");
        }
        asm volatile("cp.async.commit_group;\n" ::: "memory");
    }

    const unsigned a_off = (lane & 15) * (APAD * 2) + (lane >> 4) * 16;
    const unsigned w_row = (lane & 7) | ((lane >> 4) << 3);
    const unsigned w_half = ((lane >> 3) & 1) * 16;
    const unsigned wb_hi = smb + OFF_W + (wn * 16 + w_row) * (WPAD * 2) + w_half;
    const unsigned wb_lo = wb_hi + W_SEL;

    // Bias + register cell state: cell e = q*NT + tid -> b = e>>4, jj = tid&15
    const int jj_e = tid & 15;
    float bias_r[4], creg[2];
#pragma unroll
    for (int g = 0; g < 4; g++) bias_r[g] = bias[g * Hq + nt * 16 + jj_e];
    creg[0] = 0.f; creg[1] = 0.f;

    asm volatile("cp.async.wait_group 0;\n" ::: "memory");
    __syncthreads();

    float* gp0 = (float*)(sm + OFF_G);
    float* gp1 = (float*)(sm + OFF_G + G_SEL);
    float* gpw = wk ? gp1 : gp0;

#pragma unroll 1
    for (int t = 0; t < Tq; ++t) {
        const int p = t & 1;
        const u16* Ah = g_Ahi[p];
        const u16* Al = g_Alo[p];

        copy_chunk(smb, 0, 0, Ah, Al, bbase, tid);
        copy_chunk(smb, 1, 1, Ah, Al, bbase, tid);

        float acc[4][4];   // [mt*2 + nsub][4]
#pragma unroll
        for (int i = 0; i < 4; i++)
#pragma unroll
            for (int j = 0; j < 4; j++) acc[i][j] = 0.f;

#pragma unroll 1
        for (int c = 0; c < NCHK; ++c) {
            if (c < NCHK - 1) asm volatile("cp.async.wait_group 1;\n" ::: "memory");
            else              asm volatile("cp.async.wait_group 0;\n" ::: "memory");
            __syncthreads();

            const unsigned abase_hi = smb + OFF_A + (c & 1) * A_SLOT + a_off;
            const unsigned abase_lo = abase_hi + A_SEL;
            const unsigned kb2 = (unsigned)c * 256;   // W byte offset of chunk

#pragma unroll
            for (int s = 0; s < 4; s++) {
                const unsigned ka = (unsigned)(2 * s + wk) * 32;
                u32 ah0[4], ah1[4], al0[4], al1[4], wh[4], wl[4];
                ldsm4(ah0, abase_hi + ka);
                ldsm4(ah1, abase_hi + 16 * (APAD * 2) + ka);
                ldsm4(al0, abase_lo + ka);
                ldsm4(al1, abase_lo + 16 * (APAD * 2) + ka);
                ldsm4(wh, wb_hi + kb2 + ka);
                ldsm4(wl, wb_lo + kb2 + ka);
                mma16816(acc[0], ah0, wh);  mma16816(acc[1], ah0, wh + 2);
                mma16816(acc[2], ah1, wh);  mma16816(acc[3], ah1, wh + 2);
                mma16816(acc[0], ah0, wl);  mma16816(acc[1], ah0, wl + 2);
                mma16816(acc[2], ah1, wl);  mma16816(acc[3], ah1, wl + 2);
                mma16816(acc[0], al0, wh);  mma16816(acc[1], al0, wh + 2);
                mma16816(acc[2], al1, wh);  mma16816(acc[3], al1, wh + 2);
            }
            __syncthreads();
            if (c + 2 < NCHK)
                copy_chunk(smb, c & 1, c + 2, Ah, Al, bbase, tid);
        }

        // Stage per-k-parity partial gates
#pragma unroll
        for (int mt = 0; mt < 2; mt++)
#pragma unroll
            for (int nsub = 0; nsub < 2; nsub++) {
                const float* a4 = acc[mt * 2 + nsub];
                int m = mt * 16 + (lane >> 2);
                int col = wn * 16 + nsub * 8 + (lane & 3) * 2;
                *(float2*)&gpw[m * GPAD + col] = make_float2(a4[0], a4[1]);
                *(float2*)&gpw[(m + 8) * GPAD + col] = make_float2(a4[2], a4[3]);
            }

        // x conversion for step t+1 (this block owns batch row `blk`)
        if (t + 1 < Tq && tid < Dq) {
            float v = x[((size_t)blk * Tq + (t + 1)) * Dq + tid];
            u16 hi, lo; split_bf16(v, hi, lo);
            g_Ahi[p ^ 1][blk * KTOT + Hq + tid] = hi;
            g_Alo[p ^ 1][blk * KTOT + Hq + tid] = lo;
        }
        __syncthreads();

        // Elementwise LSTM: 2 cells per thread (b = q*16 + tid>>4, jj = tid&15)
#pragma unroll
        for (int q = 0; q < 2; q++) {
            int b = q * 16 + (tid >> 4);
            int gb = b * GPAD + jj_e;
            float gi = gp0[gb]      + gp1[gb]      + bias_r[0];
            float gf = gp0[gb + 16] + gp1[gb + 16] + bias_r[1];
            float gg = gp0[gb + 32] + gp1[gb + 32] + bias_r[2];
            float go = gp0[gb + 48] + gp1[gb + 48] + bias_r[3];
            float cn = sigm(gf) * creg[q] + sigm(gi) * tanh_fast(gg);
            creg[q] = cn;
            float h = sigm(go) * tanh_fast(cn);
            u16 hi, lo; split_bf16(h, hi, lo);
            size_t gidx = (size_t)(bbase + b) * KTOT + nt * 16 + jj_e;
            g_Ahi[p ^ 1][gidx] = hi;
            g_Alo[p ^ 1][gidx] = lo;
        }

        // Per-bt-group barrier (32 blocks)
        __threadfence();
        __syncthreads();
        if (tid == 0) {
            atomicAdd((unsigned*)barp, 1u);
            unsigned target = (unsigned)(t + 1) * 32u;
            while (*barp < target) { }
        }
        __syncthreads();
    }

    // Output head: nt==0 block of each group handles its own 32 rows.
    if (nt == 0) {
        float* hst = (float*)sm;            // 32x512 fp32 (over W region)
        float* lst = hst + 32 * Hq;
        const int rbase = bbase;
        __syncthreads();
        for (int i = tid; i < 32 * Hq; i += NT) {
            int b = i >> 9, k = i & 511;
            size_t gi = (size_t)(rbase + b) * KTOT + k;
            hst[i] = __bfloat162float(__ushort_as_bfloat16(g_Ahi[0][gi])) +
                     __bfloat162float(__ushort_as_bfloat16(g_Alo[0][gi]));
        }
        __syncthreads();
        for (int q = tid; q < 32 * Lq; q += NT) {
            int b = q / Lq, l = q - b * Lq;
            const float* hr = hst + b * Hq;
            const float* wr = Wout + l * Hq;
            float s = 0.f;
            for (int k = 0; k < Hq; k++) s += hr[k] * wr[k];
            lst[q] = s;
        }
        __syncthreads();
        if (tid < 32) {
            int b = tid;
            float m = -1e30f;
            for (int l = 0; l < Lq; l++) m = fmaxf(m, lst[b * Lq + l]);
            float e[Lq]; float ssum = 0.f;
            for (int l = 0; l < Lq; l++) { e[l] = expf(lst[b * Lq + l] - m); ssum += e[l]; }
            float inv = 1.f / ssum;
            for (int l = 0; l < Lq; l++) out[(rbase + b) * Lq + l] = e[l] * inv;
        }
    }
}

extern "C" void kernel_launch(void* const* d_in, const int* in_sizes, int n_in,
                              void* d_out, int out_size) {
    const float* x     = (const float*)d_in[0];
    const float* W_ih  = (const float*)d_in[1];
    const float* W_hh  = (const float*)d_in[2];
    const float* b     = (const float*)d_in[3];
    const float* W_out = (const float*)d_in[4];
    float* out = (float*)d_out;

    cudaFuncSetAttribute(lstm_kernel,
                         cudaFuncAttributeMaxDynamicSharedMemorySize, SMEM_BYTES);

    init_kernel<<<256, 256>>>(x, W_ih, W_hh);
    lstm_kernel<<<NBLK, NT, SMEM_BYTES>>>(x, b, W_out, out);
}